// round 4
// baseline (speedup 1.0000x reference)
#include <cuda_runtime.h>

#define NBOX 4096
#define T 256
#define PER 16                 // NBOX / T
#define NWARP (T / 32)         // 8
#define THRESH 0.05f

// x1-sorted boxes; per-iteration read is one L1-resident line (broadcast)
__device__ float4 g_sbox[NBOX];

__global__ __launch_bounds__(T, 1)
void softnms_kernel(const float4* __restrict__ boxes,
                    const float*  __restrict__ scores,
                    float* __restrict__ out, int out_size)
{
    __shared__ unsigned long long skv[NBOX];  // (x1bits << 32) | sorted pos
    __shared__ uint2 swarp[2][NWARP];         // double-buffered per-warp argmax
    __shared__ int   slast;                   // last selected original index

    const int t    = threadIdx.x;
    const int lane = t & 31;
    const int wid  = t >> 5;

    // ---- init: zero score outputs, stage u64 sort keys ----
#pragma unroll
    for (int k = 0; k < PER; k++) {
        const int gi = t * PER + k;
        if (gi < out_size) out[gi] = 0.0f;
        // x1 >= 0 -> float bits are monotone under unsigned compare
        skv[gi] = ((unsigned long long)__float_as_uint(boxes[gi].x) << 32)
                  | (unsigned)gi;
    }
    __syncthreads();

    // ---- bitonic sort ascending on u64 key ----
    for (int k = 2; k <= NBOX; k <<= 1) {
        for (int j = k >> 1; j > 0; j >>= 1) {
            for (int e = t; e < NBOX; e += T) {
                const int ixj = e ^ j;
                if (ixj > e) {
                    const unsigned long long a = skv[e], c = skv[ixj];
                    const bool up = ((e & k) == 0);
                    if (up ? (a > c) : (a < c)) { skv[e] = c; skv[ixj] = a; }
                }
            }
            __syncthreads();
        }
    }

    // ---- load my PER sorted boxes into registers; publish sorted boxes ----
    float x1[PER], y1[PER], x2[PER], y2[PER], area[PER], s[PER];
    int   orig[PER];
    unsigned procm = 0;
    float tx2hi = 0.0f;
#pragma unroll
    for (int k = 0; k < PER; k++) {
        const int pos = t * PER + k;
        const int o   = (int)(unsigned)(skv[pos] & 0xffffffffu);
        orig[k] = o;
        const float4 b = boxes[o];
        x1[k] = b.x; y1[k] = b.y; x2[k] = b.z; y2[k] = b.w;
        area[k] = (b.z - b.x) * (b.w - b.y);
        s[k]    = scores[o];
        g_sbox[pos] = b;
        tx2hi = fmaxf(tx2hi, b.z);
    }
    const float tx1lo = x1[0];   // slab is x1-ascending -> first is min
    __syncthreads();             // g_sbox settled (block-scope fence)

    unsigned cm = 0, cwp = 0;    // cached warp-level (maxbits, pos)
    bool dirty = true;
    int  step  = 0;

    for (; step < NBOX; step++) {
        // ---- warp argmax: rebuild only if some lane's scores changed ----
        if (__ballot_sync(0xffffffffu, dirty)) {
            unsigned bb = 0, bp = 0;
#pragma unroll
            for (int k = 0; k < PER; k++) {
                if (!((procm >> k) & 1u)) {
                    const unsigned ub = __float_as_uint(s[k]);   // scores > 0
                    if (ub > bb) { bb = ub; bp = t * PER + k; }
                }
            }
            const unsigned m   = __reduce_max_sync(0xffffffffu, bb);
            const unsigned bal = __ballot_sync(0xffffffffu, bb == m);
            cwp = __shfl_sync(0xffffffffu, bp, __ffs(bal) - 1);
            cm  = m;
            dirty = false;
        }
        if (lane == 0) swarp[step & 1][wid] = make_uint2(cm, cwp);
        __syncthreads();   // the ONLY barrier per iteration

        // ---- every warp redundantly reduces the 8 warp entries ----
        const uint2 v     = swarp[step & 1][lane & (NWARP - 1)];  // dup-read ok
        const unsigned m2 = __reduce_max_sync(0xffffffffu, v.x);
        const unsigned b2 = __ballot_sync(0xffffffffu, v.x == m2);
        const int selpos  = (int)__shfl_sync(0xffffffffu, v.y, __ffs(b2) - 1);
        const float sel   = __uint_as_float(m2);

        // owner records selected index (original numbering)
        if ((selpos >> 4) == t) {            // selpos / PER == t
            const int o = orig[selpos & (PER - 1)];
            if ((NBOX + step) < out_size) out[NBOX + step] = (float)o;
            slast = o;
        }

        if (!(sel > THRESH)) break;          // state frozen from here on

        const float4 b = g_sbox[selpos];     // same-address L1 broadcast

        // ---- thread-level x-interval skip (exact: reject => inter == 0) ----
        if (b.x <= tx2hi && b.z >= tx1lo) {
            const float ai = (b.z - b.x) * (b.w - b.y);
#pragma unroll
            for (int k = 0; k < PER; k++) {
                if ((procm >> k) & 1u) continue;
                const int pos = t * PER + k;
                if (pos == selpos) {
                    procm |= 1u << k;
                    if (orig[k] < out_size) out[orig[k]] = sel;  // selection score
                    dirty = true;
                } else {
                    const float xx1 = fmaxf(b.x, x1[k]);
                    const float yy1 = fmaxf(b.y, y1[k]);
                    const float xx2 = fminf(b.z, x2[k]);
                    const float yy2 = fminf(b.w, y2[k]);
                    const float iw  = fmaxf(xx2 - xx1, 0.0f);
                    const float ih  = fmaxf(yy2 - yy1, 0.0f);
                    const float inter = iw * ih;
                    if (inter > 0.0f) {
                        const float iou = __fdividef(inter, ai + area[k] - inter);
                        s[k] *= __expf(-2.0f * iou * iou);
                        dirty = true;
                    }
                }
            }
        }
        // next iteration uses the other swarp buffer -> one barrier suffices
    }

    // ---- early-exit: all remaining steps re-select the frozen argmax ----
    __syncthreads();
    if (step < NBOX) {
        const int fo = slast;
        for (int j = step + 1 + t; j < NBOX; j += T) {
            if ((NBOX + j) < out_size) out[NBOX + j] = (float)fo;
        }
    }
}

extern "C" void kernel_launch(void* const* d_in, const int* in_sizes, int n_in,
                              void* d_out, int out_size)
{
    const float4* boxes;
    const float*  scores;
    if (in_sizes[0] == 4 * NBOX) {
        boxes  = (const float4*)d_in[0];
        scores = (const float*)d_in[1];
    } else {
        boxes  = (const float4*)d_in[1];
        scores = (const float*)d_in[0];
    }
    softnms_kernel<<<1, T>>>(boxes, scores, (float*)d_out, out_size);
}

// round 5
// speedup vs baseline: 3.1775x; 3.1775x over previous
#include <cuda_runtime.h>

#define NBOX 4096
#define T 1024
#define PER 4                  // NBOX / T
#define NWARP 32               // T / 32
#define BMAX 16
#define THRESH 0.05f
#define FULL 0xffffffffu

// x1-sorted boxes; scan reads are same-address L1 broadcasts
__device__ float4 g_sbox[NBOX];

__global__ __launch_bounds__(T, 1)
void softnms_kernel(const float4* __restrict__ boxes,
                    const float*  __restrict__ scores,
                    float* __restrict__ out, int out_size)
{
    __shared__ unsigned long long skv[NBOX];  // (x1bits<<32) | orig, sorted
    __shared__ uint4 spool[2][NWARP];         // per-warp (m1,p1,m2,p2), dbl-buf

    const int t    = threadIdx.x;
    const int lane = t & 31;
    const int wid  = t >> 5;

    // ---- init: zero score outputs, stage u64 sort keys ----
#pragma unroll
    for (int k = 0; k < PER; k++) {
        const int gi = t * PER + k;
        if (gi < out_size) out[gi] = 0.0f;
        skv[gi] = ((unsigned long long)__float_as_uint(boxes[gi].x) << 32)
                  | (unsigned)gi;
    }
    __syncthreads();

    // ---- bitonic sort ascending on u64 key (x1) ----
    for (int k = 2; k <= NBOX; k <<= 1) {
        for (int j = k >> 1; j > 0; j >>= 1) {
#pragma unroll
            for (int e = t; e < NBOX; e += T) {
                const int ixj = e ^ j;
                if (ixj > e) {
                    const unsigned long long a = skv[e], c = skv[ixj];
                    const bool up = ((e & k) == 0);
                    if (up ? (a > c) : (a < c)) { skv[e] = c; skv[ixj] = a; }
                }
            }
            __syncthreads();
        }
    }

    // ---- load my PER sorted boxes; publish sorted box table ----
    float x1[PER], y1[PER], x2[PER], y2[PER], area[PER], s[PER];
    int   orig[PER];
    unsigned procm = 0;
    float tx2hi = 0.0f;
#pragma unroll
    for (int k = 0; k < PER; k++) {
        const int pos = t * PER + k;
        const int o   = (int)(unsigned)(skv[pos] & 0xffffffffu);
        orig[k] = o;
        const float4 b = boxes[o];
        x1[k] = b.x; y1[k] = b.y; x2[k] = b.z; y2[k] = b.w;
        area[k] = (b.z - b.x) * (b.w - b.y);
        s[k]    = scores[o];
        g_sbox[pos] = b;
        tx2hi = fmaxf(tx2hi, b.z);
    }
    const float tx1lo = x1[0];      // slab is x1-ascending
    __syncthreads();                // g_sbox + skv settled

    uint4 cpool = make_uint4(0u, 0u, 0u, 0u);   // cached warp top-2
    bool dirty  = true;
    bool frozen = false;
    int  fpos   = 0;
    int  step   = 0;
    int  it     = 0;

    while (step < NBOX) {
        // ---- rebuild warp top-2 only if some lane's state changed ----
        if (__ballot_sync(FULL, dirty)) {
            unsigned bb = 0, bp = 0, sb = 0, sp = 0;
#pragma unroll
            for (int k = 0; k < PER; k++) {
                if (!((procm >> k) & 1u)) {
                    const unsigned ub = __float_as_uint(s[k]);   // scores > 0
                    const unsigned up = (unsigned)(t * PER + k);
                    if (ub > bb)      { sb = bb; sp = bp; bb = ub; bp = up; }
                    else if (ub > sb) { sb = ub; sp = up; }
                }
            }
            const unsigned m1  = __reduce_max_sync(FULL, bb);
            const unsigned b1  = __ballot_sync(FULL, bb == m1);
            const int src1     = __ffs(b1) - 1;
            const unsigned p1  = __shfl_sync(FULL, bp, src1);
            const unsigned v2  = (lane == src1) ? sb : bb;
            const unsigned c2p = (lane == src1) ? sp : bp;
            const unsigned m2  = __reduce_max_sync(FULL, v2);
            const unsigned b2  = __ballot_sync(FULL, v2 == m2);
            const int src2     = __ffs(b2) - 1;
            const unsigned p2  = __shfl_sync(FULL, c2p, src2);
            cpool = make_uint4(m1, p1, m2, p2);
            dirty = false;
        }
        if (lane == 0) spool[it & 1][wid] = cpool;
        __syncthreads();    // the ONLY barrier per batch-iteration

        // ---- warp-cooperative greedy batch scan (all warps, redundant) ----
        const uint4 pe = spool[it & 1][lane];   // lane i = warp i's entry
        unsigned key = pe.x, pos = pe.y;
        unsigned nk  = pe.z, np  = pe.w;
        int state = 0;                           // 0: offering m1, 1: m2, 2: done
        int B = 0;
        float ax1 = 0.f, ay1 = 0.f, ax2 = 0.f, ay2 = 0.f;  // my batch slot
        unsigned apos = 0u, asc = 0u;

        while (true) {
            const unsigned m = __reduce_max_sync(FULL, key);
            if (m == 0u) break;                  // nothing representable left
            const float sel = __uint_as_float(m);
            const unsigned balc = __ballot_sync(FULL, key == m);
            const int srcc = __ffs(balc) - 1;
            const unsigned psel = __shfl_sync(FULL, pos, srcc);

            if (!(sel > THRESH)) {               // sub-threshold argmax
                if (B == 0) { frozen = true; fpos = (int)psel; }
                break;                            // (if B>0: recheck next iter)
            }

            const float4 b = g_sbox[psel];       // broadcast load

            // overlap vs already-accepted batch members (lane j holds slot j)
            const bool ov = (lane < B)
                && (fminf(b.z, ax2) > fmaxf(b.x, ax1))
                && (fminf(b.w, ay2) > fmaxf(b.y, ay1));
            if (__ballot_sync(FULL, ov)) break;  // would be decayed first

            // ---- accept candidate as batch member B ----
            if (lane == B) { ax1 = b.x; ay1 = b.y; ax2 = b.z; ay2 = b.w;
                             apos = psel; asc = m; }
            if (wid == 0 && lane == 0 && (NBOX + step + B) < out_size) {
                const int o = (int)(unsigned)(skv[psel] & 0xffffffffu);
                out[NBOX + step + B] = (float)o;
            }
            const int st_src = __shfl_sync(FULL, state, srcc);
            if (lane == srcc) {
                if (state == 0) { key = nk; pos = np; state = 1; }
                else            { key = 0u; state = 2; }
            }
            B++;
            if (st_src == 1) break;   // that warp's #3 unrepresented -> stop
            if (B == BMAX) break;
        }

        if (B == 0) break;            // frozen (or done) -> exit outer loop

        // ---- apply batch decay: my PER boxes vs all B accepted ----
        for (int j = 0; j < B; j++) {
            const float bx1 = __shfl_sync(FULL, ax1, j);
            const float by1 = __shfl_sync(FULL, ay1, j);
            const float bx2 = __shfl_sync(FULL, ax2, j);
            const float by2 = __shfl_sync(FULL, ay2, j);
            const unsigned pj  = __shfl_sync(FULL, apos, j);
            const unsigned scj = __shfl_sync(FULL, asc,  j);
            if (bx1 <= tx2hi && bx2 >= tx1lo) {   // x-interval skip (exact)
                const float ai = (bx2 - bx1) * (by2 - by1);
#pragma unroll
                for (int k = 0; k < PER; k++) {
                    if ((procm >> k) & 1u) continue;
                    const int posk = t * PER + k;
                    if (posk == (int)pj) {
                        procm |= 1u << k;
                        if (orig[k] < out_size)
                            out[orig[k]] = __uint_as_float(scj);
                        dirty = true;
                    } else {
                        const float xx1 = fmaxf(bx1, x1[k]);
                        const float yy1 = fmaxf(by1, y1[k]);
                        const float xx2 = fminf(bx2, x2[k]);
                        const float yy2 = fminf(by2, y2[k]);
                        const float iw  = fmaxf(xx2 - xx1, 0.0f);
                        const float ih  = fmaxf(yy2 - yy1, 0.0f);
                        const float inter = iw * ih;
                        if (inter > 0.0f) {
                            const float iou =
                                __fdividef(inter, ai + area[k] - inter);
                            s[k] *= __expf(-2.0f * iou * iou);
                            dirty = true;
                        }
                    }
                }
            }
        }
        step += B;
        it++;
    }

    // ---- frozen tail: every remaining step re-selects the same argmax ----
    if (frozen && step < NBOX) {
        const int fo = (int)(unsigned)(skv[fpos] & 0xffffffffu);
        for (int j = step + t; j < NBOX; j += T) {
            if ((NBOX + j) < out_size) out[NBOX + j] = (float)fo;
        }
    }
}

extern "C" void kernel_launch(void* const* d_in, const int* in_sizes, int n_in,
                              void* d_out, int out_size)
{
    const float4* boxes;
    const float*  scores;
    if (in_sizes[0] == 4 * NBOX) {
        boxes  = (const float4*)d_in[0];
        scores = (const float*)d_in[1];
    } else {
        boxes  = (const float4*)d_in[1];
        scores = (const float*)d_in[0];
    }
    softnms_kernel<<<1, T>>>(boxes, scores, (float*)d_out, out_size);
}

// round 6
// speedup vs baseline: 3.3922x; 1.0676x over previous
#include <cuda_runtime.h>

#define NBOX 4096
#define T 1024
#define PER 4                  // NBOX / T
#define NWARP 32
#define BMAX 32
#define THRESH 0.05f
#define FULL 0xffffffffu

// x1-sorted boxes + sorted-pos -> original index (L1-resident)
__device__ float4 g_sbox[NBOX];
__device__ int    g_orig[NBOX];

__global__ __launch_bounds__(T, 1)
void softnms_kernel(const float4* __restrict__ boxes,
                    const float*  __restrict__ scores,
                    float* __restrict__ out, int out_size)
{
    __shared__ unsigned long long skv[NBOX];   // sort scratch
    __shared__ uint4    spool[NWARP];          // per-warp (m1,p1,m2,p2)
    __shared__ unsigned sm3[NWARP];            // per-warp 3rd-best value
    __shared__ float4   sbatch_box[BMAX];      // accepted member coords
    __shared__ uint2    sbatch_meta[BMAX];     // (pos, score bits)
    __shared__ int      sB, sfro, sfpos;

    const int t    = threadIdx.x;
    const int lane = t & 31;
    const int wid  = t >> 5;

    // ---- init: zero score outputs, stage u64 sort keys ----
#pragma unroll
    for (int k = 0; k < PER; k++) {
        const int gi = t * PER + k;
        if (gi < out_size) out[gi] = 0.0f;
        skv[gi] = ((unsigned long long)__float_as_uint(boxes[gi].x) << 32)
                  | (unsigned)gi;
    }
    __syncthreads();

    // ---- bitonic sort ascending by x1 ----
    for (int k = 2; k <= NBOX; k <<= 1) {
        for (int j = k >> 1; j > 0; j >>= 1) {
#pragma unroll
            for (int e = t; e < NBOX; e += T) {
                const int ixj = e ^ j;
                if (ixj > e) {
                    const unsigned long long a = skv[e], c = skv[ixj];
                    const bool up = ((e & k) == 0);
                    if (up ? (a > c) : (a < c)) { skv[e] = c; skv[ixj] = a; }
                }
            }
            __syncthreads();
        }
    }

    // ---- load my PER sorted boxes; publish sorted tables ----
    float x1[PER], y1[PER], x2[PER], y2[PER], area[PER], s[PER];
    int   orig[PER];
    unsigned procm = 0;
    float tx2hi = 0.0f;
#pragma unroll
    for (int k = 0; k < PER; k++) {
        const int pos = t * PER + k;
        const int o   = (int)(unsigned)(skv[pos] & 0xffffffffu);
        orig[k] = o;
        const float4 b = boxes[o];
        x1[k] = b.x; y1[k] = b.y; x2[k] = b.z; y2[k] = b.w;
        area[k] = (b.z - b.x) * (b.w - b.y);
        s[k]    = scores[o];
        g_sbox[pos] = b;
        g_orig[pos] = o;
        tx2hi = fmaxf(tx2hi, b.z);
    }
    const float tx1lo = x1[0];
    __syncthreads();

    bool dirty = true;
    int  step  = 0;
    int  fro_final = 0, fpos_final = 0;

    while (step < NBOX) {
        // ================= rebuild per-warp top-2 (+3rd value) =============
        if (__ballot_sync(FULL, dirty)) {
            unsigned b1 = 0, p1 = 0, b2 = 0, p2 = 0, b3 = 0;
#pragma unroll
            for (int k = 0; k < PER; k++) {
                if (!((procm >> k) & 1u)) {
                    const unsigned ub = __float_as_uint(s[k]);   // scores > 0
                    const unsigned up = (unsigned)(t * PER + k);
                    if (ub > b1)      { b3 = b2; b2 = b1; p2 = p1; b1 = ub; p1 = up; }
                    else if (ub > b2) { b3 = b2; b2 = ub; p2 = up; }
                    else if (ub > b3) { b3 = ub; }
                }
            }
            const unsigned m1   = __reduce_max_sync(FULL, b1);
            const unsigned bal1 = __ballot_sync(FULL, b1 == m1);
            const int s1        = __ffs(bal1) - 1;
            const unsigned q1   = __shfl_sync(FULL, p1, s1);
            const unsigned v2   = (lane == s1) ? b2 : b1;
            const unsigned vp2  = (lane == s1) ? p2 : p1;
            const unsigned m2   = __reduce_max_sync(FULL, v2);
            const unsigned bal2 = __ballot_sync(FULL, v2 == m2);
            const int s2        = __ffs(bal2) - 1;
            const unsigned q2   = __shfl_sync(FULL, vp2, s2);
            unsigned v3 = b1;
            if (lane == s1) v3 = b2;
            if (lane == s2) v3 = (s2 == s1) ? b3 : b2;
            const unsigned m3 = __reduce_max_sync(FULL, v3);
            if (lane == 0) { spool[wid] = make_uint4(m1, q1, m2, q2); sm3[wid] = m3; }
            dirty = false;
        }
        __syncthreads();   // bar1: pools visible

        // ================= warp-0 batch scan (decay-and-continue) ==========
        if (wid == 0) {
            uint4 e = spool[lane];                     // lane <-> warp
            unsigned k1 = e.x, pp1 = e.y, k2 = e.z, pp2 = e.w;
            const unsigned M3 = __reduce_max_sync(FULL, sm3[lane]);
            // preload entry coords + areas (pool keys stay exact via decay)
            float4 f1 = g_sbox[pp1]; const float a1 = (f1.z - f1.x) * (f1.w - f1.y);
            float4 f2 = g_sbox[pp2]; const float a2 = (f2.z - f2.x) * (f2.w - f2.y);

            int B = 0, fz = 0; unsigned fp = 0;
            while (true) {
                const unsigned lk = (k1 > k2) ? k1 : k2;
                const unsigned m  = __reduce_max_sync(FULL, lk);
                if (m < M3) break;                     // representability lost
                const unsigned bal = __ballot_sync(FULL, lk == m);
                const int src      = __ffs(bal) - 1;
                const bool slot1   = (k1 == m);
                const unsigned psel = __shfl_sync(FULL, slot1 ? pp1 : pp2, src);
                const float sel = __uint_as_float(m);
                if (!(sel > THRESH)) {                 // true argmax <= thresh
                    if (B == 0) { fz = 1; fp = psel; }
                    break;
                }
                // broadcast member coords from src lane's registers
                const float mx1 = __shfl_sync(FULL, slot1 ? f1.x : f2.x, src);
                const float my1 = __shfl_sync(FULL, slot1 ? f1.y : f2.y, src);
                const float mx2 = __shfl_sync(FULL, slot1 ? f1.z : f2.z, src);
                const float my2 = __shfl_sync(FULL, slot1 ? f1.w : f2.w, src);
                const float mar = (mx2 - mx1) * (my2 - my1);
                if (lane == src) {
                    sbatch_box[B]  = make_float4(mx1, my1, mx2, my2);
                    sbatch_meta[B] = make_uint2(psel, m);
                    if ((NBOX + step + B) < out_size)
                        out[NBOX + step + B] = (float)g_orig[psel];
                    if (slot1) k1 = 0u; else k2 = 0u;  // consume
                }
                // decay both pool entries vs member — bit-identical to thread path
                if (k1 != 0u) {
                    const float iw = fmaxf(fminf(mx2, f1.z) - fmaxf(mx1, f1.x), 0.0f);
                    const float ih = fmaxf(fminf(my2, f1.w) - fmaxf(my1, f1.y), 0.0f);
                    const float inter = iw * ih;
                    if (inter > 0.0f) {
                        const float iou = __fdividef(inter, mar + a1 - inter);
                        k1 = __float_as_uint(__uint_as_float(k1) *
                                             __expf(-2.0f * iou * iou));
                    }
                }
                if (k2 != 0u) {
                    const float iw = fmaxf(fminf(mx2, f2.z) - fmaxf(mx1, f2.x), 0.0f);
                    const float ih = fmaxf(fminf(my2, f2.w) - fmaxf(my1, f2.y), 0.0f);
                    const float inter = iw * ih;
                    if (inter > 0.0f) {
                        const float iou = __fdividef(inter, mar + a2 - inter);
                        k2 = __float_as_uint(__uint_as_float(k2) *
                                             __expf(-2.0f * iou * iou));
                    }
                }
                B++;
                if (B == BMAX) break;
            }
            if (lane == 0) { sB = B; sfro = fz; sfpos = (int)fp; }
        }
        __syncthreads();   // bar2: batch visible

        const int Bn = sB;
        if (sfro) { fro_final = 1; fpos_final = sfpos; break; }
        if (Bn == 0) continue;     // M3 resync (rebuild happened via dirty warps? force-safe)

        // ================= apply batch decay (all threads) =================
        for (int j = 0; j < Bn; j++) {
            const float4 mb = sbatch_box[j];       // LDS broadcast
            const uint2  mm = sbatch_meta[j];
            if (mb.x <= tx2hi && mb.z >= tx1lo) {  // x-interval skip (exact)
                const float mar = (mb.z - mb.x) * (mb.w - mb.y);
#pragma unroll
                for (int k = 0; k < PER; k++) {
                    if ((procm >> k) & 1u) continue;
                    const int posk = t * PER + k;
                    if (posk == (int)mm.x) {
                        procm |= 1u << k;
                        if (orig[k] < out_size)
                            out[orig[k]] = __uint_as_float(mm.y);
                        dirty = true;
                    } else {
                        const float iw = fmaxf(fminf(mb.z, x2[k]) - fmaxf(mb.x, x1[k]), 0.0f);
                        const float ih = fmaxf(fminf(mb.w, y2[k]) - fmaxf(mb.y, y1[k]), 0.0f);
                        const float inter = iw * ih;
                        if (inter > 0.0f) {
                            const float iou = __fdividef(inter, mar + area[k] - inter);
                            s[k] *= __expf(-2.0f * iou * iou);
                            dirty = true;
                        }
                    }
                }
            }
        }
        step += Bn;
    }

    // ---- frozen tail: remaining steps all re-select the same argmax ----
    if (fro_final && step < NBOX) {
        const int fo = g_orig[fpos_final];
        for (int j = step + t; j < NBOX; j += T) {
            if ((NBOX + j) < out_size) out[NBOX + j] = (float)fo;
        }
    }
}

extern "C" void kernel_launch(void* const* d_in, const int* in_sizes, int n_in,
                              void* d_out, int out_size)
{
    const float4* boxes;
    const float*  scores;
    if (in_sizes[0] == 4 * NBOX) {
        boxes  = (const float4*)d_in[0];
        scores = (const float*)d_in[1];
    } else {
        boxes  = (const float4*)d_in[1];
        scores = (const float*)d_in[0];
    }
    softnms_kernel<<<1, T>>>(boxes, scores, (float*)d_out, out_size);
}